// round 15
// baseline (speedup 1.0000x reference)
#include <cuda_runtime.h>
#include <cuda_fp16.h>
#include <math.h>
#include <stdint.h>

// ---------------------------------------------------------------------------
// Problem constants
// ---------------------------------------------------------------------------
#define BATCH 16
#define CDIM  64
#define HW    4096
#define NROWS 65536           // BATCH*HW
#define KCODE 512
#define TPB   256             // rows per CTA (8 warps x 32 rows)
#define NBLK  (NROWS / TPB)   // 256 CTAs

// d_out layout (float32): out[4194304] | commit | perp | active | indices[65536]
#define OUT_ELEMS   (BATCH * CDIM * HW)
#define COMMIT_OFF  OUT_ELEMS
#define PERP_OFF    (OUT_ELEMS + 1)
#define ACT_OFF     (OUT_ELEMS + 2)
#define IDX_OFF     (OUT_ELEMS + 3)

// Row layout in smem (uint32 words of half2): 32 hi + 32 lo + 4 pad = 68 words.
// Fragment read bank = (4*row + word) % 32 -> bijective over (lr, lc): no conflicts.
#define WPAD 68
#define FLT_BIG 3.402823e38f

// Scratch (zero-init at load; g_hist re-zeroed at end of vq_finalize)
__device__ int   g_hist[KCODE];
__device__ float g_partial[NBLK];

// ---------------------------------------------------------------------------
__device__ __forceinline__ void mma_f16(float* d, const uint32_t* a,
                                        uint32_t b0, uint32_t b1) {
    asm volatile(
        "mma.sync.aligned.m16n8k16.row.col.f32.f16.f16.f32 "
        "{%0,%1,%2,%3}, {%4,%5,%6,%7}, {%8,%9}, {%0,%1,%2,%3};"
        : "+f"(d[0]), "+f"(d[1]), "+f"(d[2]), "+f"(d[3])
        : "r"(a[0]), "r"(a[1]), "r"(a[2]), "r"(a[3]), "r"(b0), "r"(b1));
}

__device__ __forceinline__ uint32_t pack_h2(__half a, __half b) {
    __half2 h = __halves2half2(a, b);
    return *(uint32_t*)&h;
}
__device__ __forceinline__ float2 unpack_h2(uint32_t w) {
    __half2 h = *(__half2*)&w;
    return __half22float2(h);
}

// ---------------------------------------------------------------------------
// dynamic smem layout (bytes):
#define OFF_XS   0                     // 256*68*4 = 69632  (x hi+lo planes)
#define OFF_ES   69632                 // 512*68*4 = 139264 (e hi+lo planes)
#define OFF_E2   208896                // 512 f32
#define OFF_HIST 210944                // 512 int
#define OFF_BIDX 212992                // 256 int
#define OFF_X2   214016                // 256 f32
#define OFF_RED  215040                // 8 f32
#define OFF_LIST 215072                // 256 int (recheck rows)
#define OFF_CNT  216096                // [0]=count, [1]=e2max bits
#define SMEM_BYTES 216112

extern __shared__ char s_raw[];

__global__ __launch_bounds__(TPB, 1)
void vq_main(const float* __restrict__ in,
             const float* __restrict__ emb,
             float* __restrict__ out) {
    uint32_t* xsu   = (uint32_t*)(s_raw + OFF_XS);
    uint32_t* esu   = (uint32_t*)(s_raw + OFF_ES);
    float* e2s      = (float*)(s_raw + OFF_E2);
    int*   s_hist   = (int*)(s_raw + OFF_HIST);
    int*   s_bidx   = (int*)(s_raw + OFF_BIDX);
    float* s_x2     = (float*)(s_raw + OFF_X2);
    float* s_red    = (float*)(s_raw + OFF_RED);
    int*   s_list   = (int*)(s_raw + OFF_LIST);
    int*   s_scal   = (int*)(s_raw + OFF_CNT);

    const int tid  = threadIdx.x;
    const int wid  = tid >> 5;
    const int lane = tid & 31;
    const int lr   = lane >> 2;   // 0..7
    const int lc   = lane & 3;    // 0..3
    const int mbase = wid * 32;

    const int n  = blockIdx.x * TPB + tid;  // this thread's row
    const int b  = n >> 12;
    const int hw = n & 4095;

    if (tid == 0) { s_scal[0] = 0; s_scal[1] = 0; }
    __syncthreads();

    // ---- load x row (BCHW strided, coalesced across lanes), x2, split+stage ----
    const float* xin = in + (size_t)b * CDIM * HW + hw;
    float x2 = 0.f;
    {
        float xr[CDIM];
        #pragma unroll
        for (int c = 0; c < CDIM; c++) {
            xr[c] = xin[(size_t)c * HW];
            x2 += xr[c] * xr[c];
        }
        const int rb = tid * WPAD;
        #pragma unroll
        for (int w0 = 0; w0 < 32; w0++) {
            const int w = (w0 + tid) & 31;       // rotate: conflict-free writes
            float v0 = xr[2 * w], v1 = xr[2 * w + 1];
            __half h0 = __float2half_rn(v0), h1 = __float2half_rn(v1);
            __half l0 = __float2half_rn(v0 - __half2float(h0));
            __half l1 = __float2half_rn(v1 - __half2float(h1));
            xsu[rb + w]      = pack_h2(h0, h1);
            xsu[rb + 32 + w] = pack_h2(l0, l1);
        }
        s_x2[tid] = x2;
    }

    // ---- stage codebook split planes (warp-cooperative, conflict-free) ----
    for (int c = wid; c < KCODE; c += 8) {
        const float2 v = ((const float2*)(emb + c * CDIM))[lane];
        __half h0 = __float2half_rn(v.x), h1 = __float2half_rn(v.y);
        __half l0 = __float2half_rn(v.x - __half2float(h0));
        __half l1 = __float2half_rn(v.y - __half2float(h1));
        esu[c * WPAD + lane]      = pack_h2(h0, h1);
        esu[c * WPAD + 32 + lane] = pack_h2(l0, l1);
    }

    // ---- e2 from global, e2max, hist init ----
    float e2max_loc = 0.f;
    #pragma unroll
    for (int i = tid; i < KCODE; i += TPB) {
        const float4* e4 = (const float4*)(emb + i * CDIM);
        float s = 0.f;
        #pragma unroll
        for (int j = 0; j < CDIM / 4; j++) {
            float4 e = e4[j];
            s += e.x * e.x + e.y * e.y + e.z * e.z + e.w * e.w;
        }
        e2s[i] = s;
        s_hist[i] = 0;
        if (s > e2max_loc) e2max_loc = s;
    }
    atomicMax(&s_scal[1], __float_as_int(e2max_loc));  // norms > 0: int order ok
    __syncthreads();

    const float e2max = __int_as_float(s_scal[1]);

    // ---- SCREEN: fp16 hi-only mma, track best1(+idx) and best2 per slot ----
    float b1[4] = {FLT_BIG, FLT_BIG, FLT_BIG, FLT_BIG};
    float b2[4] = {FLT_BIG, FLT_BIG, FLT_BIG, FLT_BIG};
    int   i1[4] = {0, 0, 0, 0};

    for (int cb = 0; cb < KCODE; cb += 64) {
        float acc[2][8][4];
        #pragma unroll
        for (int mt = 0; mt < 2; mt++)
            #pragma unroll
            for (int nt = 0; nt < 8; nt++)
                #pragma unroll
                for (int r = 0; r < 4; r++) acc[mt][nt][r] = 0.f;

        #pragma unroll
        for (int ks = 0; ks < 4; ks++) {        // K = 4 x 16
            const int wb = 8 * ks + lc;

            uint32_t ah[2][4];
            #pragma unroll
            for (int mt = 0; mt < 2; mt++) {
                const int r0 = (mbase + mt * 16 + lr) * WPAD;
                const int r1 = r0 + 8 * WPAD;
                ah[mt][0] = xsu[r0 + wb];     ah[mt][1] = xsu[r1 + wb];
                ah[mt][2] = xsu[r0 + wb + 4]; ah[mt][3] = xsu[r1 + wb + 4];
            }
            uint32_t bh[8][2];
            #pragma unroll
            for (int nt = 0; nt < 8; nt++) {
                const int c0 = (cb + nt * 8 + lr) * WPAD;
                bh[nt][0] = esu[c0 + wb];
                bh[nt][1] = esu[c0 + wb + 4];
            }
            #pragma unroll
            for (int nt = 0; nt < 8; nt++) {
                mma_f16(acc[0][nt], ah[0], bh[nt][0], bh[nt][1]);
                mma_f16(acc[1][nt], ah[1], bh[nt][0], bh[nt][1]);
            }
        }

        // chunk epilogue: d~ = e2 - 2*dot~, track best1/best2 (cols ascending)
        #pragma unroll
        for (int nt = 0; nt < 8; nt++) {
            const int col0 = cb + nt * 8 + lc * 2;
            const float e20 = e2s[col0];
            const float e21 = e2s[col0 + 1];
            #pragma unroll
            for (int mt = 0; mt < 2; mt++) {
                #pragma unroll
                for (int h = 0; h < 2; h++) {
                    const int slot = mt * 2 + h;
                    float d0 = fmaf(-2.f, acc[mt][nt][2*h    ], e20);
                    float d1 = fmaf(-2.f, acc[mt][nt][2*h + 1], e21);
                    if (d0 < b1[slot]) { b2[slot] = b1[slot]; b1[slot] = d0; i1[slot] = col0; }
                    else if (d0 < b2[slot]) b2[slot] = d0;
                    if (d1 < b1[slot]) { b2[slot] = b1[slot]; b1[slot] = d1; i1[slot] = col0 + 1; }
                    else if (d1 < b2[slot]) b2[slot] = d1;
                }
            }
        }
    }

    // ---- quad reduce (merge best1/best2, tie -> lower idx) ----
    #pragma unroll
    for (int s = 0; s < 4; s++) {
        #pragma unroll
        for (int off = 1; off <= 2; off <<= 1) {
            float ob1 = __shfl_xor_sync(0xFFFFFFFFu, b1[s], off);
            float ob2 = __shfl_xor_sync(0xFFFFFFFFu, b2[s], off);
            int   oi1 = __shfl_xor_sync(0xFFFFFFFFu, i1[s], off);
            float nb2 = fminf(fmaxf(b1[s], ob1), fminf(b2[s], ob2));
            if (ob1 < b1[s] || (ob1 == b1[s] && oi1 < i1[s])) { b1[s] = ob1; i1[s] = oi1; }
            b2[s] = nb2;
        }
    }
    if (lc == 0) {
        #pragma unroll
        for (int s = 0; s < 4; s++) {
            const int row = mbase + ((s & 1) << 3) + ((s >> 1) << 4) + lr;
            s_bidx[row] = i1[s];
            // certification: sound error bound for fp16 hi-only screen
            float eps = 0.0021f * sqrtf(s_x2[row] * e2max) + 1e-5f;
            if (b2[s] - b1[s] <= 2.f * eps) {
                int p = atomicAdd(&s_scal[0], 1);
                s_list[p] = row;
            }
        }
    }
    __syncthreads();

    // ---- cooperative exact recheck of uncertified rows (warp per row) ----
    {
        const int cnt = s_scal[0];
        for (int li = wid; li < cnt; li += 8) {
            const int row = s_list[li];
            // reconstruct x (broadcast reads, all lanes same addr)
            float xr[CDIM];
            #pragma unroll
            for (int w = 0; w < 32; w++) {
                float2 h = unpack_h2(xsu[row * WPAD + w]);
                float2 l = unpack_h2(xsu[row * WPAD + 32 + w]);
                xr[2 * w]     = h.x + l.x;
                xr[2 * w + 1] = h.y + l.y;
            }
            float bv = FLT_BIG; int bi = 0;
            #pragma unroll 2
            for (int j = 0; j < 16; j++) {
                const int c = lane + 32 * j;     // per-lane ascending
                float dot = 0.f;
                #pragma unroll
                for (int w = 0; w < 32; w++) {
                    float2 h = unpack_h2(esu[c * WPAD + w]);
                    float2 l = unpack_h2(esu[c * WPAD + 32 + w]);
                    dot = fmaf(xr[2 * w],     h.x + l.x, dot);
                    dot = fmaf(xr[2 * w + 1], h.y + l.y, dot);
                }
                float d = e2s[c] - 2.f * dot;
                if (d < bv) { bv = d; bi = c; }
            }
            #pragma unroll
            for (int off = 16; off > 0; off >>= 1) {
                float ov = __shfl_xor_sync(0xFFFFFFFFu, bv, off);
                int   oi = __shfl_xor_sync(0xFFFFFFFFu, bi, off);
                if (ov < bv || (ov == bv && oi < bi)) { bv = ov; bi = oi; }
            }
            if (lane == 0) s_bidx[row] = bi;
        }
    }
    __syncthreads();

    // ---- per-row epilogue (row = tid): exact distance for winner ----
    const int kbest = s_bidx[tid];
    float dot = 0.f;
    #pragma unroll
    for (int w = 0; w < 32; w++) {
        float2 xh = unpack_h2(xsu[tid * WPAD + w]);
        float2 xl = unpack_h2(xsu[tid * WPAD + 32 + w]);
        float2 eh = unpack_h2(esu[kbest * WPAD + w]);
        float2 el = unpack_h2(esu[kbest * WPAD + 32 + w]);
        dot = fmaf(xh.x + xl.x, eh.x + el.x, dot);
        dot = fmaf(xh.y + xl.y, eh.y + el.y, dot);
    }
    const float dexact = x2 + (e2s[kbest] - 2.f * dot);

    atomicAdd(&s_hist[kbest], 1);
    out[IDX_OFF + n] = (float)kbest;

    {   // scatter exact fp32 code row from global (codebook is L2-hot)
        float* op = out + (size_t)b * CDIM * HW + hw;
        const float4* eb = (const float4*)(emb + kbest * CDIM);
        #pragma unroll
        for (int j = 0; j < CDIM / 4; j++) {
            float4 e = eb[j];
            op[(size_t)(4 * j + 0) * HW] = e.x;
            op[(size_t)(4 * j + 1) * HW] = e.y;
            op[(size_t)(4 * j + 2) * HW] = e.z;
            op[(size_t)(4 * j + 3) * HW] = e.w;
        }
    }

    // commitment partial
    float dsum = dexact;
    #pragma unroll
    for (int off = 16; off > 0; off >>= 1)
        dsum += __shfl_down_sync(0xFFFFFFFFu, dsum, off);
    if (lane == 0) s_red[wid] = dsum;
    __syncthreads();
    if (tid == 0) {
        float t = 0.f;
        #pragma unroll
        for (int w = 0; w < TPB / 32; w++) t += s_red[w];
        g_partial[blockIdx.x] = t;
    }
    for (int i = tid; i < KCODE; i += TPB) {
        int h = s_hist[i];
        if (h) atomicAdd(&g_hist[i], h);
    }
}

// ---------------------------------------------------------------------------
// Kernel 2: finalize scalars (re-zeroes g_hist for the next graph replay)
// ---------------------------------------------------------------------------
__global__ void vq_finalize(const float* __restrict__ weight,
                            float* __restrict__ out) {
    __shared__ float red[KCODE];
    const int t = threadIdx.x;  // 512

    int   hcount = g_hist[t];
    g_hist[t] = 0;
    float p = (float)hcount * (1.0f / (float)NROWS);
    red[t] = p * logf(p + 1e-10f);
    __syncthreads();
    #pragma unroll
    for (int s = KCODE / 2; s > 0; s >>= 1) {
        if (t < s) red[t] += red[t + s];
        __syncthreads();
    }
    float ent = red[0];
    __syncthreads();

    red[t] = (t < NBLK) ? g_partial[t] : 0.f;
    __syncthreads();
    #pragma unroll
    for (int s = KCODE / 2; s > 0; s >>= 1) {
        if (t < s) red[t] += red[t + s];
        __syncthreads();
    }
    float csum = red[0];
    __syncthreads();

    red[t] = (weight[t] >= 0.01f) ? 1.f : 0.f;
    __syncthreads();
    #pragma unroll
    for (int s = KCODE / 2; s > 0; s >>= 1) {
        if (t < s) red[t] += red[t + s];
        __syncthreads();
    }

    if (t == 0) {
        out[COMMIT_OFF] = csum * (1.0f / (float)OUT_ELEMS);
        out[PERP_OFF]   = expf(-ent);
        out[ACT_OFF]    = red[0];
    }
}

// ---------------------------------------------------------------------------
extern "C" void kernel_launch(void* const* d_in, const int* in_sizes, int n_in,
                              void* d_out, int out_size) {
    const float* in     = (const float*)d_in[0];
    const float* emb    = (const float*)d_in[1];
    const float* weight = (const float*)d_in[2];
    float*       out    = (float*)d_out;

    cudaFuncSetAttribute(vq_main, cudaFuncAttributeMaxDynamicSharedMemorySize,
                         SMEM_BYTES);

    vq_main<<<NBLK, TPB, SMEM_BYTES>>>(in, emb, out);
    vq_finalize<<<1, KCODE>>>(weight, out);
}

// round 16
// speedup vs baseline: 2.6141x; 2.6141x over previous
#include <cuda_runtime.h>
#include <cuda_fp16.h>
#include <math.h>
#include <stdint.h>

// ---------------------------------------------------------------------------
// Problem constants
// ---------------------------------------------------------------------------
#define BATCH 16
#define CDIM  64
#define HW    4096
#define NROWS 65536           // BATCH*HW
#define KCODE 512
#define TPB   256             // 8 warps
#define GRID  148             // persistent: one CTA per SM
#define TILE_ROWS 64
#define NTILES (NROWS / TILE_ROWS)   // 1024

// d_out layout (float32): out[4194304] | commit | perp | active | indices[65536]
#define OUT_ELEMS   (BATCH * CDIM * HW)
#define COMMIT_OFF  OUT_ELEMS
#define PERP_OFF    (OUT_ELEMS + 1)
#define ACT_OFF     (OUT_ELEMS + 2)
#define IDX_OFF     (OUT_ELEMS + 3)

// Row layout in smem (uint32 words of half2): 32 hi + 32 lo + 4 pad = 68 words.
// Fragment read bank = (4*row + word) % 32 -> bijective over (lr, lc): no conflicts.
#define WPAD 68
#define FLT_BIG 3.402823e38f

// Scratch (zero-init at load; g_hist re-zeroed at end of vq_finalize)
__device__ int   g_hist[KCODE];
__device__ float g_partial[GRID];

// ---------------------------------------------------------------------------
__device__ __forceinline__ void mma_f16(float* d, const uint32_t* a,
                                        uint32_t b0, uint32_t b1) {
    asm volatile(
        "mma.sync.aligned.m16n8k16.row.col.f32.f16.f16.f32 "
        "{%0,%1,%2,%3}, {%4,%5,%6,%7}, {%8,%9}, {%0,%1,%2,%3};"
        : "+f"(d[0]), "+f"(d[1]), "+f"(d[2]), "+f"(d[3])
        : "r"(a[0]), "r"(a[1]), "r"(a[2]), "r"(a[3]), "r"(b0), "r"(b1));
}

__device__ __forceinline__ uint32_t pack_h2(__half a, __half b) {
    __half2 h = __halves2half2(a, b);
    return *(uint32_t*)&h;
}
__device__ __forceinline__ float2 unpack_h2(uint32_t w) {
    __half2 h = *(__half2*)&w;
    return __half22float2(h);
}
__device__ __forceinline__ uint32_t split_pack_hi(float v0, float v1,
                                                  uint32_t* lo) {
    __half h0 = __float2half_rn(v0), h1 = __float2half_rn(v1);
    __half l0 = __float2half_rn(v0 - __half2float(h0));
    __half l1 = __float2half_rn(v1 - __half2float(h1));
    *lo = pack_h2(l0, l1);
    return pack_h2(h0, h1);
}

// ---------------------------------------------------------------------------
// dynamic smem layout (bytes)
#define OFF_XS    0                       // 64*68*4  = 17408  (x tile planes)
#define OFF_ES    17408                   // 512*68*4 = 139264 (codebook planes)
#define OFF_E2    156672                  // 512 f32
#define OFF_HIST  158720                  // 512 int
#define OFF_BESTH 160768                  // 128 f32  (2 halves x 64 rows)
#define OFF_BIDXH 161280                  // 128 int
#define OFF_CRED  161792                  // 256 f32
#define SMEM_BYTES 162816

extern __shared__ char s_raw[];

__global__ __launch_bounds__(TPB, 1)
void vq_main(const float* __restrict__ in,
             const float* __restrict__ emb,
             float* __restrict__ out) {
    uint32_t* xsu    = (uint32_t*)(s_raw + OFF_XS);
    uint32_t* esu    = (uint32_t*)(s_raw + OFF_ES);
    float* e2s       = (float*)(s_raw + OFF_E2);
    int*   s_hist    = (int*)(s_raw + OFF_HIST);
    float* s_bestH   = (float*)(s_raw + OFF_BESTH);
    int*   s_bidxH   = (int*)(s_raw + OFF_BIDXH);
    float* s_cred    = (float*)(s_raw + OFF_CRED);

    const int tid  = threadIdx.x;
    const int wid  = tid >> 5;
    const int lane = tid & 31;
    const int lr   = lane >> 2;   // 0..7
    const int lc   = lane & 3;    // 0..3
    const int half = wid >> 2;            // code half: 0 or 1
    const int wrow = (wid & 3) * 16;      // warp's 16-row base in tile
    const int row4 = tid >> 2;            // row handled by this thread (0..63)
    const int j4   = tid & 3;             // channel-quarter within row

    // ---- stage codebook split planes once (warp-cooperative, conflict-free) ----
    for (int c = wid; c < KCODE; c += 8) {
        const float2 v = ((const float2*)(emb + c * CDIM))[lane];
        uint32_t lo;
        uint32_t hi = split_pack_hi(v.x, v.y, &lo);
        esu[c * WPAD + lane]      = hi;
        esu[c * WPAD + 32 + lane] = lo;
    }
    // e2 + hist init
    #pragma unroll
    for (int i = tid; i < KCODE; i += TPB) {
        const float4* e4 = (const float4*)(emb + i * CDIM);
        float s = 0.f;
        #pragma unroll
        for (int j = 0; j < CDIM / 4; j++) {
            float4 e = e4[j];
            s += e.x * e.x + e.y * e.y + e.z * e.z + e.w * e.w;
        }
        e2s[i] = s;
        s_hist[i] = 0;
    }

    float creg = 0.f;   // commitment accumulator (only j4==0 lanes add)

    // ---- persistent tile loop: 1024 tiles of 64 rows ----
    for (int tile = blockIdx.x; tile < NTILES; tile += GRID) {
        __syncthreads();   // xsu/s_bestH free from previous tile's readers

        // stage x tile: 4 threads per row, 16 channels each
        const int n  = tile * TILE_ROWS + row4;
        const int b  = n >> 12;
        const int hw = n & 4095;
        const float* xin = in + (size_t)b * CDIM * HW + hw;

        float x2 = 0.f;
        {
            const int wb = row4 * WPAD + j4 * 8;
            #pragma unroll
            for (int i = 0; i < 8; i++) {
                const int c0 = j4 * 16 + 2 * i;
                float v0 = xin[(size_t)c0 * HW];
                float v1 = xin[(size_t)(c0 + 1) * HW];
                x2 += v0 * v0 + v1 * v1;
                uint32_t lo;
                uint32_t hi = split_pack_hi(v0, v1, &lo);
                xsu[wb + i]      = hi;
                xsu[wb + 32 + i] = lo;
            }
            x2 += __shfl_xor_sync(0xFFFFFFFFu, x2, 1);
            x2 += __shfl_xor_sync(0xFFFFFFFFu, x2, 2);   // full row x2 in quad
        }
        __syncthreads();

        // ---- GEMM: warp = 16 rows x 256 codes (its half), fp16 3-split ----
        float best[2] = {FLT_BIG, FLT_BIG};
        int   bidx[2] = {0, 0};

        #pragma unroll
        for (int cc = 0; cc < 4; cc++) {
            const int cb = half * 256 + cc * 64;
            float acc[8][4];
            #pragma unroll
            for (int nt = 0; nt < 8; nt++)
                #pragma unroll
                for (int r = 0; r < 4; r++) acc[nt][r] = 0.f;

            #pragma unroll
            for (int ks = 0; ks < 4; ks++) {
                const int wb = 8 * ks + lc;
                const int r0 = (wrow + lr) * WPAD;
                const int r1 = r0 + 8 * WPAD;

                uint32_t ah[4], al[4];
                ah[0] = xsu[r0 + wb];          ah[1] = xsu[r1 + wb];
                ah[2] = xsu[r0 + wb + 4];      ah[3] = xsu[r1 + wb + 4];
                al[0] = xsu[r0 + 32 + wb];     al[1] = xsu[r1 + 32 + wb];
                al[2] = xsu[r0 + 32 + wb + 4]; al[3] = xsu[r1 + 32 + wb + 4];

                uint32_t bh[8][2], bl[8][2];
                #pragma unroll
                for (int nt = 0; nt < 8; nt++) {
                    const int c0 = (cb + nt * 8 + lr) * WPAD;
                    bh[nt][0] = esu[c0 + wb];      bh[nt][1] = esu[c0 + wb + 4];
                    bl[nt][0] = esu[c0 + 32 + wb]; bl[nt][1] = esu[c0 + 32 + wb + 4];
                }
                // same per-accumulator order as R14: hi*hi, hi*lo, lo*hi
                #pragma unroll
                for (int nt = 0; nt < 8; nt++)
                    mma_f16(acc[nt], ah, bh[nt][0], bh[nt][1]);
                #pragma unroll
                for (int nt = 0; nt < 8; nt++)
                    mma_f16(acc[nt], ah, bl[nt][0], bl[nt][1]);
                #pragma unroll
                for (int nt = 0; nt < 8; nt++)
                    mma_f16(acc[nt], al, bh[nt][0], bh[nt][1]);
            }

            // chunk epilogue: d = e2 - 2*dot, running argmin (cols ascending)
            #pragma unroll
            for (int nt = 0; nt < 8; nt++) {
                const int col0 = cb + nt * 8 + lc * 2;
                const float e20 = e2s[col0];
                const float e21 = e2s[col0 + 1];
                float d0 = fmaf(-2.f, acc[nt][0], e20);
                float d1 = fmaf(-2.f, acc[nt][1], e21);
                float d2 = fmaf(-2.f, acc[nt][2], e20);
                float d3 = fmaf(-2.f, acc[nt][3], e21);
                if (d0 < best[0]) { best[0] = d0; bidx[0] = col0; }
                if (d1 < best[0]) { best[0] = d1; bidx[0] = col0 + 1; }
                if (d2 < best[1]) { best[1] = d2; bidx[1] = col0; }
                if (d3 < best[1]) { best[1] = d3; bidx[1] = col0 + 1; }
            }
        }

        // quad reduce over lc (tie -> lower idx)
        #pragma unroll
        for (int s = 0; s < 2; s++) {
            #pragma unroll
            for (int off = 1; off <= 2; off <<= 1) {
                float ov = __shfl_xor_sync(0xFFFFFFFFu, best[s], off);
                int   oi = __shfl_xor_sync(0xFFFFFFFFu, bidx[s], off);
                if (ov < best[s] || (ov == best[s] && oi < bidx[s])) {
                    best[s] = ov; bidx[s] = oi;
                }
            }
        }
        if (lc == 0) {
            s_bestH[half * 64 + wrow + lr]     = best[0];
            s_bidxH[half * 64 + wrow + lr]     = bidx[0];
            s_bestH[half * 64 + wrow + lr + 8] = best[1];
            s_bidxH[half * 64 + wrow + lr + 8] = bidx[1];
        }
        __syncthreads();

        // ---- per-row epilogue: 4 threads per row ----
        const float v0 = s_bestH[row4];
        const float v1 = s_bestH[64 + row4];
        const int   kbest = (v1 < v0) ? s_bidxH[64 + row4] : s_bidxH[row4];

        // exact dot partial over this thread's 16 channels (hi+lo reconstruct)
        float dotp = 0.f;
        {
            const int xb = row4 * WPAD + j4 * 8;
            const int eb = kbest * WPAD + j4 * 8;
            #pragma unroll
            for (int i = 0; i < 8; i++) {
                float2 xh = unpack_h2(xsu[xb + i]);
                float2 xl = unpack_h2(xsu[xb + 32 + i]);
                float2 eh = unpack_h2(esu[eb + i]);
                float2 el = unpack_h2(esu[eb + 32 + i]);
                dotp = fmaf(xh.x + xl.x, eh.x + el.x, dotp);
                dotp = fmaf(xh.y + xl.y, eh.y + el.y, dotp);
            }
            dotp += __shfl_xor_sync(0xFFFFFFFFu, dotp, 1);
            dotp += __shfl_xor_sync(0xFFFFFFFFu, dotp, 2);
        }

        if (j4 == 0) {
            creg += x2 + (e2s[kbest] - 2.f * dotp);
            atomicAdd(&s_hist[kbest], 1);
            out[IDX_OFF + n] = (float)kbest;
        }

        // scatter exact fp32 code (16 channels per thread, from L2-hot global)
        {
            float* op = out + (size_t)b * CDIM * HW + hw;
            const float4* ebp = (const float4*)(emb + kbest * CDIM + j4 * 16);
            #pragma unroll
            for (int i = 0; i < 4; i++) {
                float4 e = ebp[i];
                const int c0 = j4 * 16 + 4 * i;
                op[(size_t)(c0 + 0) * HW] = e.x;
                op[(size_t)(c0 + 1) * HW] = e.y;
                op[(size_t)(c0 + 2) * HW] = e.z;
                op[(size_t)(c0 + 3) * HW] = e.w;
            }
        }
    }

    // ---- CTA finalization: commitment partial + histogram flush ----
    __syncthreads();
    s_cred[tid] = creg;
    __syncthreads();
    #pragma unroll
    for (int s = TPB / 2; s > 0; s >>= 1) {
        if (tid < s) s_cred[tid] += s_cred[tid + s];
        __syncthreads();
    }
    if (tid == 0) g_partial[blockIdx.x] = s_cred[0];

    for (int i = tid; i < KCODE; i += TPB) {
        int h = s_hist[i];
        if (h) atomicAdd(&g_hist[i], h);
    }
}

// ---------------------------------------------------------------------------
// Kernel 2: finalize scalars (re-zeroes g_hist for the next graph replay)
// ---------------------------------------------------------------------------
__global__ void vq_finalize(const float* __restrict__ weight,
                            float* __restrict__ out) {
    __shared__ float red[KCODE];
    const int t = threadIdx.x;  // 512

    int   hcount = g_hist[t];
    g_hist[t] = 0;
    float p = (float)hcount * (1.0f / (float)NROWS);
    red[t] = p * logf(p + 1e-10f);
    __syncthreads();
    #pragma unroll
    for (int s = KCODE / 2; s > 0; s >>= 1) {
        if (t < s) red[t] += red[t + s];
        __syncthreads();
    }
    float ent = red[0];
    __syncthreads();

    red[t] = (t < GRID) ? g_partial[t] : 0.f;
    __syncthreads();
    #pragma unroll
    for (int s = KCODE / 2; s > 0; s >>= 1) {
        if (t < s) red[t] += red[t + s];
        __syncthreads();
    }
    float csum = red[0];
    __syncthreads();

    red[t] = (weight[t] >= 0.01f) ? 1.f : 0.f;
    __syncthreads();
    #pragma unroll
    for (int s = KCODE / 2; s > 0; s >>= 1) {
        if (t < s) red[t] += red[t + s];
        __syncthreads();
    }

    if (t == 0) {
        out[COMMIT_OFF] = csum * (1.0f / (float)OUT_ELEMS);
        out[PERP_OFF]   = expf(-ent);
        out[ACT_OFF]    = red[0];
    }
}

// ---------------------------------------------------------------------------
extern "C" void kernel_launch(void* const* d_in, const int* in_sizes, int n_in,
                              void* d_out, int out_size) {
    const float* in     = (const float*)d_in[0];
    const float* emb    = (const float*)d_in[1];
    const float* weight = (const float*)d_in[2];
    float*       out    = (float*)d_out;

    cudaFuncSetAttribute(vq_main, cudaFuncAttributeMaxDynamicSharedMemorySize,
                         SMEM_BYTES);

    vq_main<<<GRID, TPB, SMEM_BYTES>>>(in, emb, out);
    vq_finalize<<<1, KCODE>>>(weight, out);
}